// round 12
// baseline (speedup 1.0000x reference)
#include <cuda_runtime.h>
#include <cuda_fp16.h>
#include <cstdint>

// Problem constants: N=100000, E=1600000, H=8, D_IN=128, D_HEAD=16
#define NMAX 100000
#define FEAT_CTAS 444    // 3 per SM on 148 SMs
#define AGG_BLOCKS 1776  // 128-thr persistent blocks

// Scratch (allocation-free rule: __device__ globals)
__device__ __half g_feats_h[NMAX * 128];  // [N,128] fp16, 25.6 MB (L2-resident)
__device__ float  g_f1[NMAX * 8];
__device__ float  g_f2[NMAX * 8];
__device__ int    g_rowptr[NMAX + 1];
__device__ int    g_ctr;                  // persistent-agg work counter

__device__ __forceinline__ void mma_f16(float c[4], uint32_t a0, uint32_t a1,
                                        uint32_t a2, uint32_t a3,
                                        uint32_t b0, uint32_t b1) {
  asm volatile(
      "mma.sync.aligned.m16n8k16.row.col.f32.f16.f16.f32 "
      "{%0,%1,%2,%3}, {%4,%5,%6,%7}, {%8,%9}, {%0,%1,%2,%3};"
      : "+f"(c[0]), "+f"(c[1]), "+f"(c[2]), "+f"(c[3])
      : "r"(a0), "r"(a1), "r"(a2), "r"(a3), "r"(b0), "r"(b1));
}

// ---------------------------------------------------------------------------
// Fused kernel. Blocks [0, feat_ctas) = persistent feat CTAs (fp16 MMA,
// register-prefetch pipelined A staging, 3 CTAs/SM). Blocks after = rowptr.
// B = 144 cols (halves): [0..127] = Wm (n=h*16+o), [128..135] = wa1[d,h],
// [136..143] = wa2[d,h] (f1/f2 fused into the GEMM).
// ---------------------------------------------------------------------------
#define ASH 136   // A stride in halves (68 words)
#define BSH 136
#define EHS 136
#define SMEM_FEAT_TOTAL ((64 * ASH + 144 * BSH) * 2)  // 56,576 B

__global__ __launch_bounds__(256, 3) void feat_rp_kernel(
    const float* __restrict__ x, const float* __restrict__ W,
    const float* __restrict__ a1, const float* __restrict__ b1,
    const float* __restrict__ a2, const float* __restrict__ b2,
    const int* __restrict__ src,
    int n, int e_total, int rp_blocks, int n_tiles, int feat_ctas) {
  extern __shared__ char smem[];
  const int tid = threadIdx.x;

  // ---------------- rowptr role (after feat blocks) ----------------
  if ((int)blockIdx.x >= feat_ctas) {
    const int rb = blockIdx.x - feat_ctas;
    if (rb == 0 && tid == 0) g_ctr = 0;   // reset agg work counter
    int base = (rb * 256 + tid) * 4;
    if (base < e_total) {
      int cnt = min(4, e_total - base);
      int s[4];
      if (cnt == 4) {
        int4 s4 = *reinterpret_cast<const int4*>(&src[base]);
        s[0] = s4.x; s[1] = s4.y; s[2] = s4.z; s[3] = s4.w;
      } else {
        for (int j = 0; j < cnt; j++) s[j] = __ldg(&src[base + j]);
      }
      int prev = (base == 0) ? -1 : __ldg(&src[base - 1]);
      for (int j = 0; j < cnt; j++) {
        for (int v = prev + 1; v <= s[j]; v++) g_rowptr[v] = base + j;
        prev = s[j];
      }
      if (base + cnt == e_total)
        for (int v = prev + 1; v <= n; v++) g_rowptr[v] = e_total;
    }
    return;
  }

  // ---------------- persistent feat role ----------------
  __half* Ah = reinterpret_cast<__half*>(smem);
  __half* Bh = Ah + 64 * ASH;
  __half* Eh = Ah;                               // overlays A between syncs
  const uint32_t* A32 = reinterpret_cast<const uint32_t*>(Ah);
  const uint32_t* B32 = reinterpret_cast<const uint32_t*>(Bh);

  const int f    = blockIdx.x;
  const int w    = tid >> 5;
  const int lane = tid & 31;
  const int qid  = lane >> 2;     // 0..7
  const int tq   = lane & 3;      // 0..3
  const int rw   = (w & 3) * 16;  // warp row base
  const int cb   = (w >> 2) * 72; // warp col base (0 or 72)

  // Stage B once: Bh[c=h*16+o][d] = half(W[h][d][o])
  for (int i = tid; i < 4096; i += 256) {
    int h = i >> 9, d = (i >> 2) & 127, o0 = (i & 3) * 4;
    float4 v = *reinterpret_cast<const float4*>(&W[(size_t)h * 2048 + d * 16 + o0]);
    int c0 = h * 16 + o0;
    Bh[(c0 + 0) * BSH + d] = __float2half_rn(v.x);
    Bh[(c0 + 1) * BSH + d] = __float2half_rn(v.y);
    Bh[(c0 + 2) * BSH + d] = __float2half_rn(v.z);
    Bh[(c0 + 3) * BSH + d] = __float2half_rn(v.w);
  }
  // wa1/wa2 columns: Bh[128+h][d], Bh[136+h][d]
  for (int i = tid; i < 1024; i += 256) {
    int d = i >> 3, h = i & 7;
    float s1 = 0.f, s2 = 0.f;
#pragma unroll
    for (int o = 0; o < 16; o++) {
      float wv = __ldg(&W[(size_t)h * 2048 + d * 16 + o]);
      s1 = fmaf(wv, __ldg(&a1[h * 16 + o]), s1);
      s2 = fmaf(wv, __ldg(&a2[h * 16 + o]), s2);
    }
    Bh[(128 + h) * BSH + d] = __float2half_rn(s1);
    Bh[(136 + h) * BSH + d] = __float2half_rn(s2);
  }

  // Per-thread A-staging geometry: thread handles 8 (row, k4) slots
  const int ar[8] = {tid >> 5, (tid + 256) >> 5, (tid + 512) >> 5, (tid + 768) >> 5,
                     (tid + 1024) >> 5, (tid + 1280) >> 5, (tid + 1536) >> 5,
                     (tid + 1792) >> 5};
  const int ak = tid & 31;

  // Prefetch first tile into registers (fp16-converted: uint2 each)
  uint2 v[8];
  {
    int row0 = f * 64, nrows = min(64, n - row0);
#pragma unroll
    for (int u = 0; u < 8; u++) {
      float4 t = (ar[u] < nrows)
                     ? reinterpret_cast<const float4*>(x)[(size_t)(row0 + ar[u]) * 32 + ak]
                     : make_float4(0.f, 0.f, 0.f, 0.f);
      __half2 h0 = __floats2half2_rn(t.x, t.y);
      __half2 h1 = __floats2half2_rn(t.z, t.w);
      v[u] = make_uint2(*reinterpret_cast<uint32_t*>(&h0),
                        *reinterpret_cast<uint32_t*>(&h1));
    }
  }

  for (int t = f; t < n_tiles; t += feat_ctas) {
    const int row0 = t * 64;
    const int nrows = min(64, n - row0);

    // Store prefetched A regs -> smem
#pragma unroll
    for (int u = 0; u < 8; u++)
      *reinterpret_cast<uint2*>(&Ah[ar[u] * ASH + ak * 4]) = v[u];
    __syncthreads();

    float c[9][4];
#pragma unroll
    for (int nt = 0; nt < 9; nt++)
#pragma unroll
      for (int j = 0; j < 4; j++) c[nt][j] = 0.f;

    const int arow = (rw + qid) * (ASH / 2) + tq;   // word index
#pragma unroll
    for (int ks = 0; ks < 8; ks++) {
      const int kw = ks * 8;
      uint32_t a0 = A32[arow + kw];
      uint32_t a2 = A32[arow + kw + 4];
      uint32_t a1 = A32[arow + kw + 8 * (ASH / 2)];
      uint32_t a3 = A32[arow + kw + 8 * (ASH / 2) + 4];
      const uint32_t* Bp = &B32[(cb + qid) * (BSH / 2) + kw + tq];
#pragma unroll
      for (int nt = 0; nt < 9; nt++)
        mma_f16(c[nt], a0, a1, a2, a3, Bp[nt * 8 * (BSH / 2)], Bp[nt * 8 * (BSH / 2) + 4]);
    }
    __syncthreads();  // MMA reads of A done; overlay Eh

    // Prefetch NEXT tile (overlaps epilogue below)
    const int tn = t + feat_ctas;
    if (tn < n_tiles) {
      int row0n = tn * 64, nrowsn = min(64, n - row0n);
#pragma unroll
      for (int u = 0; u < 8; u++) {
        float4 tt = (ar[u] < nrowsn)
                        ? reinterpret_cast<const float4*>(x)[(size_t)(row0n + ar[u]) * 32 + ak]
                        : make_float4(0.f, 0.f, 0.f, 0.f);
        __half2 h0 = __floats2half2_rn(tt.x, tt.y);
        __half2 h1 = __floats2half2_rn(tt.z, tt.w);
        v[u] = make_uint2(*reinterpret_cast<uint32_t*>(&h0),
                          *reinterpret_cast<uint32_t*>(&h1));
      }
    }

    // Fragments -> Eh (feats cols) or direct f1/f2 stores (cols >= 128)
    {
      const int r0 = rw + qid;
      const int grow0 = row0 + r0;
#pragma unroll
      for (int nt = 0; nt < 9; nt++) {
        int col = cb + nt * 8 + tq * 2;
        if (col < 128) {
          *reinterpret_cast<__half2*>(&Eh[r0 * EHS + col]) =
              __floats2half2_rn(c[nt][0], c[nt][1]);
          *reinterpret_cast<__half2*>(&Eh[(r0 + 8) * EHS + col]) =
              __floats2half2_rn(c[nt][2], c[nt][3]);
        } else if (col < 136) {
          int h = col - 128;
          float bh0 = __ldg(&b1[h]), bh1 = __ldg(&b1[h + 1]);
          if (grow0 < n) {
            g_f1[(size_t)grow0 * 8 + h]     = c[nt][0] + bh0;
            g_f1[(size_t)grow0 * 8 + h + 1] = c[nt][1] + bh1;
          }
          if (grow0 + 8 < n) {
            g_f1[(size_t)(grow0 + 8) * 8 + h]     = c[nt][2] + bh0;
            g_f1[(size_t)(grow0 + 8) * 8 + h + 1] = c[nt][3] + bh1;
          }
        } else {
          int h = col - 136;
          float bh0 = __ldg(&b2[h]), bh1 = __ldg(&b2[h + 1]);
          if (grow0 < n) {
            g_f2[(size_t)grow0 * 8 + h]     = c[nt][0] + bh0;
            g_f2[(size_t)grow0 * 8 + h + 1] = c[nt][1] + bh1;
          }
          if (grow0 + 8 < n) {
            g_f2[(size_t)(grow0 + 8) * 8 + h]     = c[nt][2] + bh0;
            g_f2[(size_t)(grow0 + 8) * 8 + h + 1] = c[nt][3] + bh1;
          }
        }
      }
    }
    __syncthreads();

    // Coalesced feats store: 64 rows x 16 uint4
    for (int task = tid; task < 1024; task += 256) {
      int r = task >> 4, seg = task & 15;
      if (r < nrows)
        *reinterpret_cast<uint4*>(&g_feats_h[(size_t)(row0 + r) * 128 + seg * 8]) =
            *reinterpret_cast<const uint4*>(&Eh[r * EHS + seg * 8]);
    }
    __syncthreads();  // Eh reads done before next A staging
  }
}

// ---------------------------------------------------------------------------
// agg: persistent warps + atomic counter (4 nodes/fetch) with NODE-DESCRIPTOR
// PREFETCH: rowptr[base..base+4] loaded once (lanes 0-4, shfl-broadcast) and
// all 4 nodes' f1 values loaded up front -> per-node start chains overlap.
// Edge-paired lanes (p = lane>>4 parity, g = lane&15 dim-group, head g>>1).
// Unclamped batch-8 main loop + adaptive clamped tail (4 or 8 slots).
// ---------------------------------------------------------------------------
template <int JN, bool CLAMP>
__device__ __forceinline__ void agg_batch(
    int e, int end, float f1h, int p, int g, int hg,
    const int* __restrict__ dst, const uint4* __restrict__ fh4,
    float acc[8], float& S) {
  int dp[JN];
#pragma unroll
  for (int j = 0; j < JN; j++) {
    int idx = e + 2 * j + p;
    dp[j] = __ldg(&dst[CLAMP ? min(idx, end - 1) : idx]);
  }
  float z[JN];
#pragma unroll
  for (int j = 0; j < JN; j++) z[j] = f1h + __ldg(&g_f2[(size_t)dp[j] * 8 + hg]);
  uint4 q[JN];
#pragma unroll
  for (int j = 0; j < JN; j++) q[j] = __ldg(&fh4[(size_t)dp[j] * 16 + g]);
#pragma unroll
  for (int j = 0; j < JN; j++) {
    float wj = __expf(fmaxf(z[j], 0.2f * z[j]));
    if (CLAMP && (e + 2 * j + p >= end)) wj = 0.f;
    float2 f0 = __half22float2(*reinterpret_cast<__half2*>(&q[j].x));
    float2 f1v = __half22float2(*reinterpret_cast<__half2*>(&q[j].y));
    float2 f2v = __half22float2(*reinterpret_cast<__half2*>(&q[j].z));
    float2 f3 = __half22float2(*reinterpret_cast<__half2*>(&q[j].w));
    acc[0] = fmaf(wj, f0.x, acc[0]); acc[1] = fmaf(wj, f0.y, acc[1]);
    acc[2] = fmaf(wj, f1v.x, acc[2]); acc[3] = fmaf(wj, f1v.y, acc[3]);
    acc[4] = fmaf(wj, f2v.x, acc[4]); acc[5] = fmaf(wj, f2v.y, acc[5]);
    acc[6] = fmaf(wj, f3.x, acc[6]); acc[7] = fmaf(wj, f3.y, acc[7]);
    S += wj;
  }
}

__device__ __forceinline__ void agg_node(
    int node, int start, int end, float f1h, int p, int g, int hg,
    const int* __restrict__ dst, const uint4* __restrict__ fh4,
    float* __restrict__ out) {
  float acc[8];
#pragma unroll
  for (int k = 0; k < 8; k++) acc[k] = 0.f;
  float S = 0.f;

  if (end > start) {
    const int rem = (end - start) & 7;
    int e = start;
    const int efull = end - rem;
    for (; e < efull; e += 8)
      agg_batch<4, false>(e, end, f1h, p, g, hg, dst, fh4, acc, S);
    if (rem) {
      if (rem <= 4)
        agg_batch<2, true>(e, end, f1h, p, g, hg, dst, fh4, acc, S);
      else
        agg_batch<4, true>(e, end, f1h, p, g, hg, dst, fh4, acc, S);
    }
  }

  S += __shfl_xor_sync(0xffffffffu, S, 16);
#pragma unroll
  for (int k = 0; k < 8; k++) acc[k] += __shfl_xor_sync(0xffffffffu, acc[k], 16);

  float inv = (end > start) ? (1.f / S) : 0.f;
  const int base = p * 4;
  float4 o;
  o.x = acc[base + 0] * inv; o.y = acc[base + 1] * inv;
  o.z = acc[base + 2] * inv; o.w = acc[base + 3] * inv;
  o.x = o.x > 0.f ? o.x : (__expf(o.x) - 1.f);
  o.y = o.y > 0.f ? o.y : (__expf(o.y) - 1.f);
  o.z = o.z > 0.f ? o.z : (__expf(o.z) - 1.f);
  o.w = o.w > 0.f ? o.w : (__expf(o.w) - 1.f);
  reinterpret_cast<float4*>(out)[(size_t)node * 32 + g * 2 + p] = o;
}

__global__ __launch_bounds__(128) void agg_kernel(
    const int* __restrict__ dst, float* __restrict__ out, int n) {
  const int lane = threadIdx.x & 31;
  const int p  = lane >> 4;
  const int g  = lane & 15;
  const int hg = g >> 1;
  const uint4* fh4 = reinterpret_cast<const uint4*>(g_feats_h);

  for (;;) {
    int base = 0;
    if (lane == 0) base = atomicAdd(&g_ctr, 4);
    base = __shfl_sync(0xffffffffu, base, 0);
    if (base >= n) break;

    // Prefetch node descriptors: rowptr[base..base+4] + f1 for 4 nodes
    int rp = 0;
    if (lane < 5) {
      int idx = min(base + lane, n);
      rp = g_rowptr[idx];
    }
    const int r0 = __shfl_sync(0xffffffffu, rp, 0);
    const int r1 = __shfl_sync(0xffffffffu, rp, 1);
    const int r2 = __shfl_sync(0xffffffffu, rp, 2);
    const int r3 = __shfl_sync(0xffffffffu, rp, 3);
    const int r4 = __shfl_sync(0xffffffffu, rp, 4);
    float f1v[4];
#pragma unroll
    for (int i = 0; i < 4; i++)
      f1v[i] = (base + i < n) ? g_f1[(size_t)(base + i) * 8 + hg] : 0.f;

    const int lim = min(4, n - base);
    const int st[5] = {r0, r1, r2, r3, r4};
#pragma unroll
    for (int i = 0; i < 4; i++) {
      if (i < lim)
        agg_node(base + i, st[i], st[i + 1], f1v[i], p, g, hg, dst, fh4, out);
    }
  }
}

// ---------------------------------------------------------------------------
extern "C" void kernel_launch(void* const* d_in, const int* in_sizes, int n_in,
                              void* d_out, int out_size) {
  const float* x  = (const float*)d_in[0];
  const float* W  = (const float*)d_in[1];
  const float* a1 = (const float*)d_in[2];
  const float* b1 = (const float*)d_in[3];
  const float* a2 = (const float*)d_in[4];
  const float* b2 = (const float*)d_in[5];
  const int*  src = (const int*)d_in[6];
  const int*  dst = (const int*)d_in[7];
  float* out = (float*)d_out;

  const int n = in_sizes[0] / 128;   // N
  const int e = in_sizes[6];         // E

  const int rp_blocks = (e + 1023) / 1024;           // 4 edges/thread
  const int n_tiles   = (n + 63) / 64;
  const int feat_ctas = (n_tiles < FEAT_CTAS) ? n_tiles : FEAT_CTAS;

  cudaFuncSetAttribute(feat_rp_kernel, cudaFuncAttributeMaxDynamicSharedMemorySize,
                       SMEM_FEAT_TOTAL);

  feat_rp_kernel<<<feat_ctas + rp_blocks, 256, SMEM_FEAT_TOTAL>>>(
      x, W, a1, b1, a2, b2, src, n, e, rp_blocks, n_tiles, feat_ctas);
  agg_kernel<<<AGG_BLOCKS, 128>>>(dst, out, n);
}

// round 13
// speedup vs baseline: 1.0207x; 1.0207x over previous
#include <cuda_runtime.h>
#include <cuda_fp16.h>
#include <cstdint>

// Problem constants: N=100000, E=1600000, H=8, D_IN=128, D_HEAD=16
#define NMAX 100000
#define FEAT_CTAS 296    // 2 per SM on 148 SMs (measured best)
#define AGG_BLOCKS 2368  // 16 blocks/SM * 148 = 64 warps/SM (regs=32 fits RF)

// Scratch (allocation-free rule: __device__ globals)
__device__ __half g_feats_h[NMAX * 128];  // [N,128] fp16, 25.6 MB (L2-resident)
__device__ float  g_f1[NMAX * 8];
__device__ float  g_f2[NMAX * 8];
__device__ int    g_rowptr[NMAX + 1];
__device__ int    g_ctr;                  // persistent-agg work counter

__device__ __forceinline__ void mma_f16(float c[4], uint32_t a0, uint32_t a1,
                                        uint32_t a2, uint32_t a3,
                                        uint32_t b0, uint32_t b1) {
  asm volatile(
      "mma.sync.aligned.m16n8k16.row.col.f32.f16.f16.f32 "
      "{%0,%1,%2,%3}, {%4,%5,%6,%7}, {%8,%9}, {%0,%1,%2,%3};"
      : "+f"(c[0]), "+f"(c[1]), "+f"(c[2]), "+f"(c[3])
      : "r"(a0), "r"(a1), "r"(a2), "r"(a3), "r"(b0), "r"(b1));
}

// ---------------------------------------------------------------------------
// Fused kernel. Blocks [0, feat_ctas) = persistent feat CTAs (fp16 MMA,
// register-prefetch pipelined A staging, 2 CTAs/SM). Blocks after = rowptr.
// B = 144 cols (halves): [0..127] = Wm (n=h*16+o), [128..135] = wa1[d,h],
// [136..143] = wa2[d,h] (f1/f2 fused into the GEMM).
// ---------------------------------------------------------------------------
#define ASH 136   // A stride in halves (68 words)
#define BSH 136
#define EHS 136
#define SMEM_FEAT_TOTAL ((64 * ASH + 144 * BSH) * 2)  // 56,576 B

__global__ __launch_bounds__(256, 2) void feat_rp_kernel(
    const float* __restrict__ x, const float* __restrict__ W,
    const float* __restrict__ a1, const float* __restrict__ b1,
    const float* __restrict__ a2, const float* __restrict__ b2,
    const int* __restrict__ src,
    int n, int e_total, int rp_blocks, int n_tiles, int feat_ctas) {
  extern __shared__ char smem[];
  const int tid = threadIdx.x;

  // ---------------- rowptr role (after feat blocks) ----------------
  if ((int)blockIdx.x >= feat_ctas) {
    const int rb = blockIdx.x - feat_ctas;
    if (rb == 0 && tid == 0) g_ctr = 0;   // reset agg work counter
    int base = (rb * 256 + tid) * 4;
    if (base < e_total) {
      int cnt = min(4, e_total - base);
      int s[4];
      if (cnt == 4) {
        int4 s4 = *reinterpret_cast<const int4*>(&src[base]);
        s[0] = s4.x; s[1] = s4.y; s[2] = s4.z; s[3] = s4.w;
      } else {
        for (int j = 0; j < cnt; j++) s[j] = __ldg(&src[base + j]);
      }
      int prev = (base == 0) ? -1 : __ldg(&src[base - 1]);
      for (int j = 0; j < cnt; j++) {
        for (int v = prev + 1; v <= s[j]; v++) g_rowptr[v] = base + j;
        prev = s[j];
      }
      if (base + cnt == e_total)
        for (int v = prev + 1; v <= n; v++) g_rowptr[v] = e_total;
    }
    return;
  }

  // ---------------- persistent feat role ----------------
  __half* Ah = reinterpret_cast<__half*>(smem);
  __half* Bh = Ah + 64 * ASH;
  __half* Eh = Ah;                               // overlays A between syncs
  const uint32_t* A32 = reinterpret_cast<const uint32_t*>(Ah);
  const uint32_t* B32 = reinterpret_cast<const uint32_t*>(Bh);

  const int f    = blockIdx.x;
  const int w    = tid >> 5;
  const int lane = tid & 31;
  const int qid  = lane >> 2;     // 0..7
  const int tq   = lane & 3;      // 0..3
  const int rw   = (w & 3) * 16;  // warp row base
  const int cb   = (w >> 2) * 72; // warp col base (0 or 72)

  // Stage B once: Bh[c=h*16+o][d] = half(W[h][d][o])
  for (int i = tid; i < 4096; i += 256) {
    int h = i >> 9, d = (i >> 2) & 127, o0 = (i & 3) * 4;
    float4 v = *reinterpret_cast<const float4*>(&W[(size_t)h * 2048 + d * 16 + o0]);
    int c0 = h * 16 + o0;
    Bh[(c0 + 0) * BSH + d] = __float2half_rn(v.x);
    Bh[(c0 + 1) * BSH + d] = __float2half_rn(v.y);
    Bh[(c0 + 2) * BSH + d] = __float2half_rn(v.z);
    Bh[(c0 + 3) * BSH + d] = __float2half_rn(v.w);
  }
  // wa1/wa2 columns: Bh[128+h][d], Bh[136+h][d]
  for (int i = tid; i < 1024; i += 256) {
    int d = i >> 3, h = i & 7;
    float s1 = 0.f, s2 = 0.f;
#pragma unroll
    for (int o = 0; o < 16; o++) {
      float wv = __ldg(&W[(size_t)h * 2048 + d * 16 + o]);
      s1 = fmaf(wv, __ldg(&a1[h * 16 + o]), s1);
      s2 = fmaf(wv, __ldg(&a2[h * 16 + o]), s2);
    }
    Bh[(128 + h) * BSH + d] = __float2half_rn(s1);
    Bh[(136 + h) * BSH + d] = __float2half_rn(s2);
  }

  // Per-thread A-staging geometry: thread handles 8 (row, k4) slots
  const int ar[8] = {tid >> 5, (tid + 256) >> 5, (tid + 512) >> 5, (tid + 768) >> 5,
                     (tid + 1024) >> 5, (tid + 1280) >> 5, (tid + 1536) >> 5,
                     (tid + 1792) >> 5};
  const int ak = tid & 31;

  // Prefetch first tile into registers (fp16-converted: uint2 each)
  uint2 v[8];
  {
    int row0 = f * 64, nrows = min(64, n - row0);
#pragma unroll
    for (int u = 0; u < 8; u++) {
      float4 t = (ar[u] < nrows)
                     ? reinterpret_cast<const float4*>(x)[(size_t)(row0 + ar[u]) * 32 + ak]
                     : make_float4(0.f, 0.f, 0.f, 0.f);
      __half2 h0 = __floats2half2_rn(t.x, t.y);
      __half2 h1 = __floats2half2_rn(t.z, t.w);
      v[u] = make_uint2(*reinterpret_cast<uint32_t*>(&h0),
                        *reinterpret_cast<uint32_t*>(&h1));
    }
  }

  for (int t = f; t < n_tiles; t += feat_ctas) {
    const int row0 = t * 64;
    const int nrows = min(64, n - row0);

    // Store prefetched A regs -> smem
#pragma unroll
    for (int u = 0; u < 8; u++)
      *reinterpret_cast<uint2*>(&Ah[ar[u] * ASH + ak * 4]) = v[u];
    __syncthreads();

    float c[9][4];
#pragma unroll
    for (int nt = 0; nt < 9; nt++)
#pragma unroll
      for (int j = 0; j < 4; j++) c[nt][j] = 0.f;

    const int arow = (rw + qid) * (ASH / 2) + tq;   // word index
#pragma unroll
    for (int ks = 0; ks < 8; ks++) {
      const int kw = ks * 8;
      uint32_t a0 = A32[arow + kw];
      uint32_t a2 = A32[arow + kw + 4];
      uint32_t a1 = A32[arow + kw + 8 * (ASH / 2)];
      uint32_t a3 = A32[arow + kw + 8 * (ASH / 2) + 4];
      const uint32_t* Bp = &B32[(cb + qid) * (BSH / 2) + kw + tq];
#pragma unroll
      for (int nt = 0; nt < 9; nt++)
        mma_f16(c[nt], a0, a1, a2, a3, Bp[nt * 8 * (BSH / 2)], Bp[nt * 8 * (BSH / 2) + 4]);
    }
    __syncthreads();  // MMA reads of A done; overlay Eh

    // Prefetch NEXT tile (overlaps epilogue below)
    const int tn = t + feat_ctas;
    if (tn < n_tiles) {
      int row0n = tn * 64, nrowsn = min(64, n - row0n);
#pragma unroll
      for (int u = 0; u < 8; u++) {
        float4 tt = (ar[u] < nrowsn)
                        ? reinterpret_cast<const float4*>(x)[(size_t)(row0n + ar[u]) * 32 + ak]
                        : make_float4(0.f, 0.f, 0.f, 0.f);
        __half2 h0 = __floats2half2_rn(tt.x, tt.y);
        __half2 h1 = __floats2half2_rn(tt.z, tt.w);
        v[u] = make_uint2(*reinterpret_cast<uint32_t*>(&h0),
                          *reinterpret_cast<uint32_t*>(&h1));
      }
    }

    // Fragments -> Eh (feats cols) or direct f1/f2 stores (cols >= 128)
    {
      const int r0 = rw + qid;
      const int grow0 = row0 + r0;
#pragma unroll
      for (int nt = 0; nt < 9; nt++) {
        int col = cb + nt * 8 + tq * 2;
        if (col < 128) {
          *reinterpret_cast<__half2*>(&Eh[r0 * EHS + col]) =
              __floats2half2_rn(c[nt][0], c[nt][1]);
          *reinterpret_cast<__half2*>(&Eh[(r0 + 8) * EHS + col]) =
              __floats2half2_rn(c[nt][2], c[nt][3]);
        } else if (col < 136) {
          int h = col - 128;
          float bh0 = __ldg(&b1[h]), bh1 = __ldg(&b1[h + 1]);
          if (grow0 < n) {
            g_f1[(size_t)grow0 * 8 + h]     = c[nt][0] + bh0;
            g_f1[(size_t)grow0 * 8 + h + 1] = c[nt][1] + bh1;
          }
          if (grow0 + 8 < n) {
            g_f1[(size_t)(grow0 + 8) * 8 + h]     = c[nt][2] + bh0;
            g_f1[(size_t)(grow0 + 8) * 8 + h + 1] = c[nt][3] + bh1;
          }
        } else {
          int h = col - 136;
          float bh0 = __ldg(&b2[h]), bh1 = __ldg(&b2[h + 1]);
          if (grow0 < n) {
            g_f2[(size_t)grow0 * 8 + h]     = c[nt][0] + bh0;
            g_f2[(size_t)grow0 * 8 + h + 1] = c[nt][1] + bh1;
          }
          if (grow0 + 8 < n) {
            g_f2[(size_t)(grow0 + 8) * 8 + h]     = c[nt][2] + bh0;
            g_f2[(size_t)(grow0 + 8) * 8 + h + 1] = c[nt][3] + bh1;
          }
        }
      }
    }
    __syncthreads();

    // Coalesced feats store: 64 rows x 16 uint4
    for (int task = tid; task < 1024; task += 256) {
      int r = task >> 4, seg = task & 15;
      if (r < nrows)
        *reinterpret_cast<uint4*>(&g_feats_h[(size_t)(row0 + r) * 128 + seg * 8]) =
            *reinterpret_cast<const uint4*>(&Eh[r * EHS + seg * 8]);
    }
    __syncthreads();  // Eh reads done before next A staging
  }
}

// ---------------------------------------------------------------------------
// agg: persistent warps + atomic counter (4 nodes/fetch) with node-descriptor
// prefetch (rowptr[base..base+4] one-shot + all f1 up front). Edge-paired
// lanes (p = lane>>4 parity, g = lane&15 dim-group, head g>>1). Unclamped
// batch-8 main loop + adaptive clamped tail (4 or 8 slots).
// ---------------------------------------------------------------------------
template <int JN, bool CLAMP>
__device__ __forceinline__ void agg_batch(
    int e, int end, float f1h, int p, int g, int hg,
    const int* __restrict__ dst, const uint4* __restrict__ fh4,
    float acc[8], float& S) {
  int dp[JN];
#pragma unroll
  for (int j = 0; j < JN; j++) {
    int idx = e + 2 * j + p;
    dp[j] = __ldg(&dst[CLAMP ? min(idx, end - 1) : idx]);
  }
  float z[JN];
#pragma unroll
  for (int j = 0; j < JN; j++) z[j] = f1h + __ldg(&g_f2[(size_t)dp[j] * 8 + hg]);
  uint4 q[JN];
#pragma unroll
  for (int j = 0; j < JN; j++) q[j] = __ldg(&fh4[(size_t)dp[j] * 16 + g]);
#pragma unroll
  for (int j = 0; j < JN; j++) {
    float wj = __expf(fmaxf(z[j], 0.2f * z[j]));
    if (CLAMP && (e + 2 * j + p >= end)) wj = 0.f;
    float2 f0 = __half22float2(*reinterpret_cast<__half2*>(&q[j].x));
    float2 f1v = __half22float2(*reinterpret_cast<__half2*>(&q[j].y));
    float2 f2v = __half22float2(*reinterpret_cast<__half2*>(&q[j].z));
    float2 f3 = __half22float2(*reinterpret_cast<__half2*>(&q[j].w));
    acc[0] = fmaf(wj, f0.x, acc[0]); acc[1] = fmaf(wj, f0.y, acc[1]);
    acc[2] = fmaf(wj, f1v.x, acc[2]); acc[3] = fmaf(wj, f1v.y, acc[3]);
    acc[4] = fmaf(wj, f2v.x, acc[4]); acc[5] = fmaf(wj, f2v.y, acc[5]);
    acc[6] = fmaf(wj, f3.x, acc[6]); acc[7] = fmaf(wj, f3.y, acc[7]);
    S += wj;
  }
}

__device__ __forceinline__ void agg_node(
    int node, int start, int end, float f1h, int p, int g, int hg,
    const int* __restrict__ dst, const uint4* __restrict__ fh4,
    float* __restrict__ out) {
  float acc[8];
#pragma unroll
  for (int k = 0; k < 8; k++) acc[k] = 0.f;
  float S = 0.f;

  if (end > start) {
    const int rem = (end - start) & 7;
    int e = start;
    const int efull = end - rem;
    for (; e < efull; e += 8)
      agg_batch<4, false>(e, end, f1h, p, g, hg, dst, fh4, acc, S);
    if (rem) {
      if (rem <= 4)
        agg_batch<2, true>(e, end, f1h, p, g, hg, dst, fh4, acc, S);
      else
        agg_batch<4, true>(e, end, f1h, p, g, hg, dst, fh4, acc, S);
    }
  }

  S += __shfl_xor_sync(0xffffffffu, S, 16);
#pragma unroll
  for (int k = 0; k < 8; k++) acc[k] += __shfl_xor_sync(0xffffffffu, acc[k], 16);

  float inv = (end > start) ? (1.f / S) : 0.f;
  const int base = p * 4;
  float4 o;
  o.x = acc[base + 0] * inv; o.y = acc[base + 1] * inv;
  o.z = acc[base + 2] * inv; o.w = acc[base + 3] * inv;
  o.x = o.x > 0.f ? o.x : (__expf(o.x) - 1.f);
  o.y = o.y > 0.f ? o.y : (__expf(o.y) - 1.f);
  o.z = o.z > 0.f ? o.z : (__expf(o.z) - 1.f);
  o.w = o.w > 0.f ? o.w : (__expf(o.w) - 1.f);
  reinterpret_cast<float4*>(out)[(size_t)node * 32 + g * 2 + p] = o;
}

__global__ __launch_bounds__(128) void agg_kernel(
    const int* __restrict__ dst, float* __restrict__ out, int n) {
  const int lane = threadIdx.x & 31;
  const int p  = lane >> 4;
  const int g  = lane & 15;
  const int hg = g >> 1;
  const uint4* fh4 = reinterpret_cast<const uint4*>(g_feats_h);

  for (;;) {
    int base = 0;
    if (lane == 0) base = atomicAdd(&g_ctr, 4);
    base = __shfl_sync(0xffffffffu, base, 0);
    if (base >= n) break;

    // Prefetch node descriptors: rowptr[base..base+4] + f1 for 4 nodes
    int rp = 0;
    if (lane < 5) {
      int idx = min(base + lane, n);
      rp = g_rowptr[idx];
    }
    const int r0 = __shfl_sync(0xffffffffu, rp, 0);
    const int r1 = __shfl_sync(0xffffffffu, rp, 1);
    const int r2 = __shfl_sync(0xffffffffu, rp, 2);
    const int r3 = __shfl_sync(0xffffffffu, rp, 3);
    const int r4 = __shfl_sync(0xffffffffu, rp, 4);
    float f1v[4];
#pragma unroll
    for (int i = 0; i < 4; i++)
      f1v[i] = (base + i < n) ? g_f1[(size_t)(base + i) * 8 + hg] : 0.f;

    const int lim = min(4, n - base);
    const int st[5] = {r0, r1, r2, r3, r4};
#pragma unroll
    for (int i = 0; i < 4; i++) {
      if (i < lim)
        agg_node(base + i, st[i], st[i + 1], f1v[i], p, g, hg, dst, fh4, out);
    }
  }
}

// ---------------------------------------------------------------------------
extern "C" void kernel_launch(void* const* d_in, const int* in_sizes, int n_in,
                              void* d_out, int out_size) {
  const float* x  = (const float*)d_in[0];
  const float* W  = (const float*)d_in[1];
  const float* a1 = (const float*)d_in[2];
  const float* b1 = (const float*)d_in[3];
  const float* a2 = (const float*)d_in[4];
  const float* b2 = (const float*)d_in[5];
  const int*  src = (const int*)d_in[6];
  const int*  dst = (const int*)d_in[7];
  float* out = (float*)d_out;

  const int n = in_sizes[0] / 128;   // N
  const int e = in_sizes[6];         // E

  const int rp_blocks = (e + 1023) / 1024;           // 4 edges/thread
  const int n_tiles   = (n + 63) / 64;
  const int feat_ctas = (n_tiles < FEAT_CTAS) ? n_tiles : FEAT_CTAS;

  cudaFuncSetAttribute(feat_rp_kernel, cudaFuncAttributeMaxDynamicSharedMemorySize,
                       SMEM_FEAT_TOTAL);

  feat_rp_kernel<<<feat_ctas + rp_blocks, 256, SMEM_FEAT_TOTAL>>>(
      x, W, a1, b1, a2, b2, src, n, e, rp_blocks, n_tiles, feat_ctas);
  agg_kernel<<<AGG_BLOCKS, 128>>>(dst, out, n);
}

// round 14
// speedup vs baseline: 1.0720x; 1.0502x over previous
#include <cuda_runtime.h>
#include <cuda_fp16.h>
#include <cstdint>

// Problem constants: N=100000, E=1600000, H=8, D_IN=128, D_HEAD=16
#define NMAX 100000
#define FEAT_CTAS 296    // 2 per SM on 148 SMs (measured best)
#define AGG_BLOCKS 2368  // 16 blocks/SM * 148
#define LOG2E 1.4426950408889634f

// Scratch (allocation-free rule: __device__ globals)
__device__ __half g_feats_h[NMAX * 128];  // [N,128] fp16, 25.6 MB (L2-resident)
__device__ float  g_f1[NMAX * 8];         // pre-scaled by log2(e)
__device__ float  g_f2[NMAX * 8];         // pre-scaled by log2(e)
__device__ int    g_rowptr[NMAX + 1];
__device__ int    g_ctr;                  // persistent-agg work counter

__device__ __forceinline__ void mma_f16(float c[4], uint32_t a0, uint32_t a1,
                                        uint32_t a2, uint32_t a3,
                                        uint32_t b0, uint32_t b1) {
  asm volatile(
      "mma.sync.aligned.m16n8k16.row.col.f32.f16.f16.f32 "
      "{%0,%1,%2,%3}, {%4,%5,%6,%7}, {%8,%9}, {%0,%1,%2,%3};"
      : "+f"(c[0]), "+f"(c[1]), "+f"(c[2]), "+f"(c[3])
      : "r"(a0), "r"(a1), "r"(a2), "r"(a3), "r"(b0), "r"(b1));
}

// Packed f32x2 helpers (FFMA2 — PTX-only path, ptxas won't auto-fuse)
__device__ __forceinline__ unsigned long long pack2(float a, float b) {
  unsigned long long r;
  asm("mov.b64 %0, {%1, %2};" : "=l"(r) : "f"(a), "f"(b));
  return r;
}
__device__ __forceinline__ void unpack2(unsigned long long v, float& a, float& b) {
  asm("mov.b64 {%0, %1}, %2;" : "=f"(a), "=f"(b) : "l"(v));
}
__device__ __forceinline__ void ffma2(unsigned long long& d,
                                      unsigned long long a, unsigned long long b) {
  asm("fma.rn.f32x2 %0, %1, %2, %0;" : "+l"(d) : "l"(a), "l"(b));
}
__device__ __forceinline__ float ex2f(float x) {
  float r; asm("ex2.approx.f32 %0, %1;" : "=f"(r) : "f"(x)); return r;
}

// ---------------------------------------------------------------------------
// Fused kernel. Blocks [0, feat_ctas) = persistent feat CTAs (fp16 MMA,
// register-prefetch pipelined A staging, 2 CTAs/SM). Blocks after = rowptr.
// B = 144 cols (halves): [0..127] = Wm (n=h*16+o), [128..135] = wa1[d,h],
// [136..143] = wa2[d,h] (f1/f2 fused into the GEMM). f1/f2 stored *log2(e).
// ---------------------------------------------------------------------------
#define ASH 136   // A stride in halves (68 words)
#define BSH 136
#define EHS 136
#define SMEM_FEAT_TOTAL ((64 * ASH + 144 * BSH) * 2)  // 56,576 B

__global__ __launch_bounds__(256, 2) void feat_rp_kernel(
    const float* __restrict__ x, const float* __restrict__ W,
    const float* __restrict__ a1, const float* __restrict__ b1,
    const float* __restrict__ a2, const float* __restrict__ b2,
    const int* __restrict__ src,
    int n, int e_total, int rp_blocks, int n_tiles, int feat_ctas) {
  extern __shared__ char smem[];
  const int tid = threadIdx.x;

  // ---------------- rowptr role (after feat blocks) ----------------
  if ((int)blockIdx.x >= feat_ctas) {
    const int rb = blockIdx.x - feat_ctas;
    if (rb == 0 && tid == 0) g_ctr = 0;   // reset agg work counter
    int base = (rb * 256 + tid) * 4;
    if (base < e_total) {
      int cnt = min(4, e_total - base);
      int s[4];
      if (cnt == 4) {
        int4 s4 = *reinterpret_cast<const int4*>(&src[base]);
        s[0] = s4.x; s[1] = s4.y; s[2] = s4.z; s[3] = s4.w;
      } else {
        for (int j = 0; j < cnt; j++) s[j] = __ldg(&src[base + j]);
      }
      int prev = (base == 0) ? -1 : __ldg(&src[base - 1]);
      for (int j = 0; j < cnt; j++) {
        for (int v = prev + 1; v <= s[j]; v++) g_rowptr[v] = base + j;
        prev = s[j];
      }
      if (base + cnt == e_total)
        for (int v = prev + 1; v <= n; v++) g_rowptr[v] = e_total;
    }
    return;
  }

  // ---------------- persistent feat role ----------------
  __half* Ah = reinterpret_cast<__half*>(smem);
  __half* Bh = Ah + 64 * ASH;
  __half* Eh = Ah;                               // overlays A between syncs
  const uint32_t* A32 = reinterpret_cast<const uint32_t*>(Ah);
  const uint32_t* B32 = reinterpret_cast<const uint32_t*>(Bh);

  const int f    = blockIdx.x;
  const int w    = tid >> 5;
  const int lane = tid & 31;
  const int qid  = lane >> 2;     // 0..7
  const int tq   = lane & 3;      // 0..3
  const int rw   = (w & 3) * 16;  // warp row base
  const int cb   = (w >> 2) * 72; // warp col base (0 or 72)

  // Stage B once: Bh[c=h*16+o][d] = half(W[h][d][o])
  for (int i = tid; i < 4096; i += 256) {
    int h = i >> 9, d = (i >> 2) & 127, o0 = (i & 3) * 4;
    float4 v = *reinterpret_cast<const float4*>(&W[(size_t)h * 2048 + d * 16 + o0]);
    int c0 = h * 16 + o0;
    Bh[(c0 + 0) * BSH + d] = __float2half_rn(v.x);
    Bh[(c0 + 1) * BSH + d] = __float2half_rn(v.y);
    Bh[(c0 + 2) * BSH + d] = __float2half_rn(v.z);
    Bh[(c0 + 3) * BSH + d] = __float2half_rn(v.w);
  }
  // wa1/wa2 columns: Bh[128+h][d], Bh[136+h][d]
  for (int i = tid; i < 1024; i += 256) {
    int d = i >> 3, h = i & 7;
    float s1 = 0.f, s2 = 0.f;
#pragma unroll
    for (int o = 0; o < 16; o++) {
      float wv = __ldg(&W[(size_t)h * 2048 + d * 16 + o]);
      s1 = fmaf(wv, __ldg(&a1[h * 16 + o]), s1);
      s2 = fmaf(wv, __ldg(&a2[h * 16 + o]), s2);
    }
    Bh[(128 + h) * BSH + d] = __float2half_rn(s1);
    Bh[(136 + h) * BSH + d] = __float2half_rn(s2);
  }

  // Per-thread A-staging geometry: thread handles 8 (row, k4) slots
  const int ar[8] = {tid >> 5, (tid + 256) >> 5, (tid + 512) >> 5, (tid + 768) >> 5,
                     (tid + 1024) >> 5, (tid + 1280) >> 5, (tid + 1536) >> 5,
                     (tid + 1792) >> 5};
  const int ak = tid & 31;

  // Prefetch first tile into registers (fp16-converted: uint2 each)
  uint2 v[8];
  {
    int row0 = f * 64, nrows = min(64, n - row0);
#pragma unroll
    for (int u = 0; u < 8; u++) {
      float4 t = (ar[u] < nrows)
                     ? reinterpret_cast<const float4*>(x)[(size_t)(row0 + ar[u]) * 32 + ak]
                     : make_float4(0.f, 0.f, 0.f, 0.f);
      __half2 h0 = __floats2half2_rn(t.x, t.y);
      __half2 h1 = __floats2half2_rn(t.z, t.w);
      v[u] = make_uint2(*reinterpret_cast<uint32_t*>(&h0),
                        *reinterpret_cast<uint32_t*>(&h1));
    }
  }

  for (int t = f; t < n_tiles; t += feat_ctas) {
    const int row0 = t * 64;
    const int nrows = min(64, n - row0);

    // Store prefetched A regs -> smem
#pragma unroll
    for (int u = 0; u < 8; u++)
      *reinterpret_cast<uint2*>(&Ah[ar[u] * ASH + ak * 4]) = v[u];
    __syncthreads();

    float c[9][4];
#pragma unroll
    for (int nt = 0; nt < 9; nt++)
#pragma unroll
      for (int j = 0; j < 4; j++) c[nt][j] = 0.f;

    const int arow = (rw + qid) * (ASH / 2) + tq;   // word index
#pragma unroll
    for (int ks = 0; ks < 8; ks++) {
      const int kw = ks * 8;
      uint32_t a0 = A32[arow + kw];
      uint32_t a2 = A32[arow + kw + 4];
      uint32_t a1 = A32[arow + kw + 8 * (ASH / 2)];
      uint32_t a3 = A32[arow + kw + 8 * (ASH / 2) + 4];
      const uint32_t* Bp = &B32[(cb + qid) * (BSH / 2) + kw + tq];
#pragma unroll
      for (int nt = 0; nt < 9; nt++)
        mma_f16(c[nt], a0, a1, a2, a3, Bp[nt * 8 * (BSH / 2)], Bp[nt * 8 * (BSH / 2) + 4]);
    }
    __syncthreads();  // MMA reads of A done; overlay Eh

    // Prefetch NEXT tile (overlaps epilogue below)
    const int tn = t + feat_ctas;
    if (tn < n_tiles) {
      int row0n = tn * 64, nrowsn = min(64, n - row0n);
#pragma unroll
      for (int u = 0; u < 8; u++) {
        float4 tt = (ar[u] < nrowsn)
                        ? reinterpret_cast<const float4*>(x)[(size_t)(row0n + ar[u]) * 32 + ak]
                        : make_float4(0.f, 0.f, 0.f, 0.f);
        __half2 h0 = __floats2half2_rn(tt.x, tt.y);
        __half2 h1 = __floats2half2_rn(tt.z, tt.w);
        v[u] = make_uint2(*reinterpret_cast<uint32_t*>(&h0),
                          *reinterpret_cast<uint32_t*>(&h1));
      }
    }

    // Fragments -> Eh (feats cols) or direct f1/f2 stores (cols >= 128).
    // f1/f2 pre-scaled by log2(e) so agg uses raw ex2.
    {
      const int r0 = rw + qid;
      const int grow0 = row0 + r0;
#pragma unroll
      for (int nt = 0; nt < 9; nt++) {
        int col = cb + nt * 8 + tq * 2;
        if (col < 128) {
          *reinterpret_cast<__half2*>(&Eh[r0 * EHS + col]) =
              __floats2half2_rn(c[nt][0], c[nt][1]);
          *reinterpret_cast<__half2*>(&Eh[(r0 + 8) * EHS + col]) =
              __floats2half2_rn(c[nt][2], c[nt][3]);
        } else if (col < 136) {
          int h = col - 128;
          float bh0 = __ldg(&b1[h]), bh1 = __ldg(&b1[h + 1]);
          if (grow0 < n) {
            g_f1[(size_t)grow0 * 8 + h]     = (c[nt][0] + bh0) * LOG2E;
            g_f1[(size_t)grow0 * 8 + h + 1] = (c[nt][1] + bh1) * LOG2E;
          }
          if (grow0 + 8 < n) {
            g_f1[(size_t)(grow0 + 8) * 8 + h]     = (c[nt][2] + bh0) * LOG2E;
            g_f1[(size_t)(grow0 + 8) * 8 + h + 1] = (c[nt][3] + bh1) * LOG2E;
          }
        } else {
          int h = col - 136;
          float bh0 = __ldg(&b2[h]), bh1 = __ldg(&b2[h + 1]);
          if (grow0 < n) {
            g_f2[(size_t)grow0 * 8 + h]     = (c[nt][0] + bh0) * LOG2E;
            g_f2[(size_t)grow0 * 8 + h + 1] = (c[nt][1] + bh1) * LOG2E;
          }
          if (grow0 + 8 < n) {
            g_f2[(size_t)(grow0 + 8) * 8 + h]     = (c[nt][2] + bh0) * LOG2E;
            g_f2[(size_t)(grow0 + 8) * 8 + h + 1] = (c[nt][3] + bh1) * LOG2E;
          }
        }
      }
    }
    __syncthreads();

    // Coalesced feats store: 64 rows x 16 uint4
    for (int task = tid; task < 1024; task += 256) {
      int r = task >> 4, seg = task & 15;
      if (r < nrows)
        *reinterpret_cast<uint4*>(&g_feats_h[(size_t)(row0 + r) * 128 + seg * 8]) =
            *reinterpret_cast<const uint4*>(&Eh[r * EHS + seg * 8]);
    }
    __syncthreads();  // Eh reads done before next A staging
  }
}

// ---------------------------------------------------------------------------
// agg: persistent warps + atomic counter (4 nodes/fetch), node-descriptor
// prefetch. Edge-paired lanes (p = lane>>4 parity, g = lane&15 dim-group,
// head g>>1). Accumulation in packed f32x2 (FFMA2): 4 packed FMA per 2-edge
// group instead of 8 scalar. Weight = ex2(max(z,0.2z)), z pre-scaled.
// ---------------------------------------------------------------------------
template <int JN, bool CLAMP>
__device__ __forceinline__ void agg_batch(
    int e, int end, float f1h, int p, int g, int hg,
    const int* __restrict__ dst, const uint4* __restrict__ fh4,
    unsigned long long acc2[4], float& S) {
  int dp[JN];
#pragma unroll
  for (int j = 0; j < JN; j++) {
    int idx = e + 2 * j + p;
    dp[j] = __ldg(&dst[CLAMP ? min(idx, end - 1) : idx]);
  }
  float z[JN];
#pragma unroll
  for (int j = 0; j < JN; j++) z[j] = f1h + __ldg(&g_f2[(size_t)dp[j] * 8 + hg]);
  uint4 q[JN];
#pragma unroll
  for (int j = 0; j < JN; j++) q[j] = __ldg(&fh4[(size_t)dp[j] * 16 + g]);
#pragma unroll
  for (int j = 0; j < JN; j++) {
    float wj = ex2f(fmaxf(z[j], 0.2f * z[j]));
    if (CLAMP && (e + 2 * j + p >= end)) wj = 0.f;
    unsigned long long wp = pack2(wj, wj);
    float2 f0 = __half22float2(*reinterpret_cast<__half2*>(&q[j].x));
    float2 f1v = __half22float2(*reinterpret_cast<__half2*>(&q[j].y));
    float2 f2v = __half22float2(*reinterpret_cast<__half2*>(&q[j].z));
    float2 f3 = __half22float2(*reinterpret_cast<__half2*>(&q[j].w));
    ffma2(acc2[0], wp, pack2(f0.x, f0.y));
    ffma2(acc2[1], wp, pack2(f1v.x, f1v.y));
    ffma2(acc2[2], wp, pack2(f2v.x, f2v.y));
    ffma2(acc2[3], wp, pack2(f3.x, f3.y));
    S += wj;
  }
}

__device__ __forceinline__ void agg_node(
    int node, int start, int end, float f1h, int p, int g, int hg,
    const int* __restrict__ dst, const uint4* __restrict__ fh4,
    float* __restrict__ out) {
  unsigned long long acc2[4] = {0ull, 0ull, 0ull, 0ull};
  float S = 0.f;

  if (end > start) {
    const int rem = (end - start) & 7;
    int e = start;
    const int efull = end - rem;
    for (; e < efull; e += 8)
      agg_batch<4, false>(e, end, f1h, p, g, hg, dst, fh4, acc2, S);
    if (rem) {
      if (rem <= 4)
        agg_batch<2, true>(e, end, f1h, p, g, hg, dst, fh4, acc2, S);
      else
        agg_batch<4, true>(e, end, f1h, p, g, hg, dst, fh4, acc2, S);
    }
  }

  float acc[8];
#pragma unroll
  for (int k = 0; k < 4; k++) unpack2(acc2[k], acc[2 * k], acc[2 * k + 1]);

  S += __shfl_xor_sync(0xffffffffu, S, 16);
#pragma unroll
  for (int k = 0; k < 8; k++) acc[k] += __shfl_xor_sync(0xffffffffu, acc[k], 16);

  float inv = (end > start) ? (1.f / S) : 0.f;
  const int base = p * 4;
  float4 o;
  o.x = acc[base + 0] * inv; o.y = acc[base + 1] * inv;
  o.z = acc[base + 2] * inv; o.w = acc[base + 3] * inv;
  o.x = o.x > 0.f ? o.x : (__expf(o.x) - 1.f);
  o.y = o.y > 0.f ? o.y : (__expf(o.y) - 1.f);
  o.z = o.z > 0.f ? o.z : (__expf(o.z) - 1.f);
  o.w = o.w > 0.f ? o.w : (__expf(o.w) - 1.f);
  reinterpret_cast<float4*>(out)[(size_t)node * 32 + g * 2 + p] = o;
}

__global__ __launch_bounds__(128) void agg_kernel(
    const int* __restrict__ dst, float* __restrict__ out, int n) {
  const int lane = threadIdx.x & 31;
  const int p  = lane >> 4;
  const int g  = lane & 15;
  const int hg = g >> 1;
  const uint4* fh4 = reinterpret_cast<const uint4*>(g_feats_h);

  for (;;) {
    int base = 0;
    if (lane == 0) base = atomicAdd(&g_ctr, 4);
    base = __shfl_sync(0xffffffffu, base, 0);
    if (base >= n) break;

    // Prefetch node descriptors: rowptr[base..base+4] + f1 for 4 nodes
    int rp = 0;
    if (lane < 5) {
      int idx = min(base + lane, n);
      rp = g_rowptr[idx];
    }
    const int r0 = __shfl_sync(0xffffffffu, rp, 0);
    const int r1 = __shfl_sync(0xffffffffu, rp, 1);
    const int r2 = __shfl_sync(0xffffffffu, rp, 2);
    const int r3 = __shfl_sync(0xffffffffu, rp, 3);
    const int r4 = __shfl_sync(0xffffffffu, rp, 4);
    float f1v[4];
#pragma unroll
    for (int i = 0; i < 4; i++)
      f1v[i] = (base + i < n) ? g_f1[(size_t)(base + i) * 8 + hg] : 0.f;

    const int lim = min(4, n - base);
    const int st[5] = {r0, r1, r2, r3, r4};
#pragma unroll
    for (int i = 0; i < 4; i++) {
      if (i < lim)
        agg_node(base + i, st[i], st[i + 1], f1v[i], p, g, hg, dst, fh4, out);
    }
  }
}

// ---------------------------------------------------------------------------
extern "C" void kernel_launch(void* const* d_in, const int* in_sizes, int n_in,
                              void* d_out, int out_size) {
  const float* x  = (const float*)d_in[0];
  const float* W  = (const float*)d_in[1];
  const float* a1 = (const float*)d_in[2];
  const float* b1 = (const float*)d_in[3];
  const float* a2 = (const float*)d_in[4];
  const float* b2 = (const float*)d_in[5];
  const int*  src = (const int*)d_in[6];
  const int*  dst = (const int*)d_in[7];
  float* out = (float*)d_out;

  const int n = in_sizes[0] / 128;   // N
  const int e = in_sizes[6];         // E

  const int rp_blocks = (e + 1023) / 1024;           // 4 edges/thread
  const int n_tiles   = (n + 63) / 64;
  const int feat_ctas = (n_tiles < FEAT_CTAS) ? n_tiles : FEAT_CTAS;

  cudaFuncSetAttribute(feat_rp_kernel, cudaFuncAttributeMaxDynamicSharedMemorySize,
                       SMEM_FEAT_TOTAL);

  feat_rp_kernel<<<feat_ctas + rp_blocks, 256, SMEM_FEAT_TOTAL>>>(
      x, W, a1, b1, a2, b2, src, n, e, rp_blocks, n_tiles, feat_ctas);
  agg_kernel<<<AGG_BLOCKS, 128>>>(dst, out, n);
}

// round 15
// speedup vs baseline: 1.1484x; 1.0713x over previous
#include <cuda_runtime.h>
#include <cuda_fp16.h>
#include <cstdint>

// Problem constants: N=100000, E=1600000, H=8, D_IN=128, D_HEAD=16
#define NMAX 100000
#define FEAT_CTAS 296    // 2 per SM on 148 SMs (measured best)
#define AGG_BLOCKS 2368  // 16 blocks/SM * 148
#define LOG2E 1.4426950408889634f

// Scratch (allocation-free rule: __device__ globals)
__device__ __half g_feats_h[NMAX * 128];  // [N,128] fp16, 25.6 MB (L2-resident)
__device__ float  g_f1[NMAX * 8];         // pre-scaled by log2(e)
__device__ float  g_f2[NMAX * 8];         // pre-scaled by log2(e)
__device__ int    g_rowptr[NMAX + 1];
__device__ int    g_ctr;                  // persistent-agg work counter

__device__ __forceinline__ void mma_f16(float c[4], uint32_t a0, uint32_t a1,
                                        uint32_t a2, uint32_t a3,
                                        uint32_t b0, uint32_t b1) {
  asm volatile(
      "mma.sync.aligned.m16n8k16.row.col.f32.f16.f16.f32 "
      "{%0,%1,%2,%3}, {%4,%5,%6,%7}, {%8,%9}, {%0,%1,%2,%3};"
      : "+f"(c[0]), "+f"(c[1]), "+f"(c[2]), "+f"(c[3])
      : "r"(a0), "r"(a1), "r"(a2), "r"(a3), "r"(b0), "r"(b1));
}

// Packed f32x2 helpers (PTX-only paths)
__device__ __forceinline__ unsigned long long pack2(float a, float b) {
  unsigned long long r;
  asm("mov.b64 %0, {%1, %2};" : "=l"(r) : "f"(a), "f"(b));
  return r;
}
__device__ __forceinline__ void unpack2(unsigned long long v, float& a, float& b) {
  asm("mov.b64 {%0, %1}, %2;" : "=f"(a), "=f"(b) : "l"(v));
}
__device__ __forceinline__ void fadd2(unsigned long long& d, unsigned long long a) {
  asm("add.rn.f32x2 %0, %0, %1;" : "+l"(d) : "l"(a));
}
__device__ __forceinline__ float ex2f(float x) {
  float r; asm("ex2.approx.f32 %0, %1;" : "=f"(r) : "f"(x)); return r;
}

// ---------------------------------------------------------------------------
// Fused kernel. Blocks [0, feat_ctas) = persistent feat CTAs (fp16 MMA,
// register-prefetch pipelined A staging, 2 CTAs/SM). Blocks after = rowptr.
// B = 144 cols (halves): [0..127] = Wm (n=h*16+o), [128..135] = wa1[d,h],
// [136..143] = wa2[d,h] (f1/f2 fused into the GEMM). f1/f2 stored *log2(e).
// ---------------------------------------------------------------------------
#define ASH 136   // A stride in halves (68 words)
#define BSH 136
#define EHS 136
#define SMEM_FEAT_TOTAL ((64 * ASH + 144 * BSH) * 2)  // 56,576 B

__global__ __launch_bounds__(256, 2) void feat_rp_kernel(
    const float* __restrict__ x, const float* __restrict__ W,
    const float* __restrict__ a1, const float* __restrict__ b1,
    const float* __restrict__ a2, const float* __restrict__ b2,
    const int* __restrict__ src,
    int n, int e_total, int rp_blocks, int n_tiles, int feat_ctas) {
  extern __shared__ char smem[];
  const int tid = threadIdx.x;

  // ---------------- rowptr role (after feat blocks) ----------------
  if ((int)blockIdx.x >= feat_ctas) {
    const int rb = blockIdx.x - feat_ctas;
    if (rb == 0 && tid == 0) g_ctr = 0;   // reset agg work counter
    int base = (rb * 256 + tid) * 4;
    if (base < e_total) {
      int cnt = min(4, e_total - base);
      int s[4];
      if (cnt == 4) {
        int4 s4 = *reinterpret_cast<const int4*>(&src[base]);
        s[0] = s4.x; s[1] = s4.y; s[2] = s4.z; s[3] = s4.w;
      } else {
        for (int j = 0; j < cnt; j++) s[j] = __ldg(&src[base + j]);
      }
      int prev = (base == 0) ? -1 : __ldg(&src[base - 1]);
      for (int j = 0; j < cnt; j++) {
        for (int v = prev + 1; v <= s[j]; v++) g_rowptr[v] = base + j;
        prev = s[j];
      }
      if (base + cnt == e_total)
        for (int v = prev + 1; v <= n; v++) g_rowptr[v] = e_total;
    }
    return;
  }

  // ---------------- persistent feat role ----------------
  __half* Ah = reinterpret_cast<__half*>(smem);
  __half* Bh = Ah + 64 * ASH;
  __half* Eh = Ah;                               // overlays A between syncs
  const uint32_t* A32 = reinterpret_cast<const uint32_t*>(Ah);
  const uint32_t* B32 = reinterpret_cast<const uint32_t*>(Bh);

  const int f    = blockIdx.x;
  const int w    = tid >> 5;
  const int lane = tid & 31;
  const int qid  = lane >> 2;     // 0..7
  const int tq   = lane & 3;      // 0..3
  const int rw   = (w & 3) * 16;  // warp row base
  const int cb   = (w >> 2) * 72; // warp col base (0 or 72)

  // Stage B once: Bh[c=h*16+o][d] = half(W[h][d][o])
  for (int i = tid; i < 4096; i += 256) {
    int h = i >> 9, d = (i >> 2) & 127, o0 = (i & 3) * 4;
    float4 v = *reinterpret_cast<const float4*>(&W[(size_t)h * 2048 + d * 16 + o0]);
    int c0 = h * 16 + o0;
    Bh[(c0 + 0) * BSH + d] = __float2half_rn(v.x);
    Bh[(c0 + 1) * BSH + d] = __float2half_rn(v.y);
    Bh[(c0 + 2) * BSH + d] = __float2half_rn(v.z);
    Bh[(c0 + 3) * BSH + d] = __float2half_rn(v.w);
  }
  // wa1/wa2 columns: Bh[128+h][d], Bh[136+h][d]
  for (int i = tid; i < 1024; i += 256) {
    int d = i >> 3, h = i & 7;
    float s1 = 0.f, s2 = 0.f;
#pragma unroll
    for (int o = 0; o < 16; o++) {
      float wv = __ldg(&W[(size_t)h * 2048 + d * 16 + o]);
      s1 = fmaf(wv, __ldg(&a1[h * 16 + o]), s1);
      s2 = fmaf(wv, __ldg(&a2[h * 16 + o]), s2);
    }
    Bh[(128 + h) * BSH + d] = __float2half_rn(s1);
    Bh[(136 + h) * BSH + d] = __float2half_rn(s2);
  }

  // Per-thread A-staging geometry: thread handles 8 (row, k4) slots
  const int ar[8] = {tid >> 5, (tid + 256) >> 5, (tid + 512) >> 5, (tid + 768) >> 5,
                     (tid + 1024) >> 5, (tid + 1280) >> 5, (tid + 1536) >> 5,
                     (tid + 1792) >> 5};
  const int ak = tid & 31;

  // Prefetch first tile into registers (fp16-converted: uint2 each)
  uint2 v[8];
  {
    int row0 = f * 64, nrows = min(64, n - row0);
#pragma unroll
    for (int u = 0; u < 8; u++) {
      float4 t = (ar[u] < nrows)
                     ? reinterpret_cast<const float4*>(x)[(size_t)(row0 + ar[u]) * 32 + ak]
                     : make_float4(0.f, 0.f, 0.f, 0.f);
      __half2 h0 = __floats2half2_rn(t.x, t.y);
      __half2 h1 = __floats2half2_rn(t.z, t.w);
      v[u] = make_uint2(*reinterpret_cast<uint32_t*>(&h0),
                        *reinterpret_cast<uint32_t*>(&h1));
    }
  }

  for (int t = f; t < n_tiles; t += feat_ctas) {
    const int row0 = t * 64;
    const int nrows = min(64, n - row0);

    // Store prefetched A regs -> smem
#pragma unroll
    for (int u = 0; u < 8; u++)
      *reinterpret_cast<uint2*>(&Ah[ar[u] * ASH + ak * 4]) = v[u];
    __syncthreads();

    float c[9][4];
#pragma unroll
    for (int nt = 0; nt < 9; nt++)
#pragma unroll
      for (int j = 0; j < 4; j++) c[nt][j] = 0.f;

    const int arow = (rw + qid) * (ASH / 2) + tq;   // word index
#pragma unroll
    for (int ks = 0; ks < 8; ks++) {
      const int kw = ks * 8;
      uint32_t a0 = A32[arow + kw];
      uint32_t a2 = A32[arow + kw + 4];
      uint32_t a1 = A32[arow + kw + 8 * (ASH / 2)];
      uint32_t a3 = A32[arow + kw + 8 * (ASH / 2) + 4];
      const uint32_t* Bp = &B32[(cb + qid) * (BSH / 2) + kw + tq];
#pragma unroll
      for (int nt = 0; nt < 9; nt++)
        mma_f16(c[nt], a0, a1, a2, a3, Bp[nt * 8 * (BSH / 2)], Bp[nt * 8 * (BSH / 2) + 4]);
    }
    __syncthreads();  // MMA reads of A done; overlay Eh

    // Prefetch NEXT tile (overlaps epilogue below)
    const int tn = t + feat_ctas;
    if (tn < n_tiles) {
      int row0n = tn * 64, nrowsn = min(64, n - row0n);
#pragma unroll
      for (int u = 0; u < 8; u++) {
        float4 tt = (ar[u] < nrowsn)
                        ? reinterpret_cast<const float4*>(x)[(size_t)(row0n + ar[u]) * 32 + ak]
                        : make_float4(0.f, 0.f, 0.f, 0.f);
        __half2 h0 = __floats2half2_rn(tt.x, tt.y);
        __half2 h1 = __floats2half2_rn(tt.z, tt.w);
        v[u] = make_uint2(*reinterpret_cast<uint32_t*>(&h0),
                          *reinterpret_cast<uint32_t*>(&h1));
      }
    }

    // Fragments -> Eh (feats cols) or direct f1/f2 stores (cols >= 128).
    {
      const int r0 = rw + qid;
      const int grow0 = row0 + r0;
#pragma unroll
      for (int nt = 0; nt < 9; nt++) {
        int col = cb + nt * 8 + tq * 2;
        if (col < 128) {
          *reinterpret_cast<__half2*>(&Eh[r0 * EHS + col]) =
              __floats2half2_rn(c[nt][0], c[nt][1]);
          *reinterpret_cast<__half2*>(&Eh[(r0 + 8) * EHS + col]) =
              __floats2half2_rn(c[nt][2], c[nt][3]);
        } else if (col < 136) {
          int h = col - 128;
          float bh0 = __ldg(&b1[h]), bh1 = __ldg(&b1[h + 1]);
          if (grow0 < n) {
            g_f1[(size_t)grow0 * 8 + h]     = (c[nt][0] + bh0) * LOG2E;
            g_f1[(size_t)grow0 * 8 + h + 1] = (c[nt][1] + bh1) * LOG2E;
          }
          if (grow0 + 8 < n) {
            g_f1[(size_t)(grow0 + 8) * 8 + h]     = (c[nt][2] + bh0) * LOG2E;
            g_f1[(size_t)(grow0 + 8) * 8 + h + 1] = (c[nt][3] + bh1) * LOG2E;
          }
        } else {
          int h = col - 136;
          float bh0 = __ldg(&b2[h]), bh1 = __ldg(&b2[h + 1]);
          if (grow0 < n) {
            g_f2[(size_t)grow0 * 8 + h]     = (c[nt][0] + bh0) * LOG2E;
            g_f2[(size_t)grow0 * 8 + h + 1] = (c[nt][1] + bh1) * LOG2E;
          }
          if (grow0 + 8 < n) {
            g_f2[(size_t)(grow0 + 8) * 8 + h]     = (c[nt][2] + bh0) * LOG2E;
            g_f2[(size_t)(grow0 + 8) * 8 + h + 1] = (c[nt][3] + bh1) * LOG2E;
          }
        }
      }
    }
    __syncthreads();

    // Coalesced feats store: 64 rows x 16 uint4
    for (int task = tid; task < 1024; task += 256) {
      int r = task >> 4, seg = task & 15;
      if (r < nrows)
        *reinterpret_cast<uint4*>(&g_feats_h[(size_t)(row0 + r) * 128 + seg * 8]) =
            *reinterpret_cast<const uint4*>(&Eh[r * EHS + seg * 8]);
    }
    __syncthreads();  // Eh reads done before next A staging
  }
}

// ---------------------------------------------------------------------------
// agg: persistent warps + atomic counter (4 nodes/fetch), node-descriptor
// prefetch. Edge-paired lanes (p = lane>>4 parity, g = lane&15 dim-group,
// head g>>1). Inner batch accumulates in HALF2 (4 HFMA2/edge, no F2F), then
// folds into packed fp32 accumulators once per batch (8 F2F + 4 FADD2).
// Weight = ex2(max(z,0.2z)), z pre-scaled by log2(e).
// ---------------------------------------------------------------------------
template <int JN, bool CLAMP>
__device__ __forceinline__ void agg_batch(
    int e, int end, float f1h, int p, int g, int hg,
    const int* __restrict__ dst, const uint4* __restrict__ fh4,
    unsigned long long acc2[4], float& S) {
  int dp[JN];
#pragma unroll
  for (int j = 0; j < JN; j++) {
    int idx = e + 2 * j + p;
    dp[j] = __ldg(&dst[CLAMP ? min(idx, end - 1) : idx]);
  }
  float z[JN];
#pragma unroll
  for (int j = 0; j < JN; j++) z[j] = f1h + __ldg(&g_f2[(size_t)dp[j] * 8 + hg]);
  uint4 q[JN];
#pragma unroll
  for (int j = 0; j < JN; j++) q[j] = __ldg(&fh4[(size_t)dp[j] * 16 + g]);

  __half2 hacc[4];
#pragma unroll
  for (int k = 0; k < 4; k++) hacc[k] = __half2half2(__ushort_as_half(0));

#pragma unroll
  for (int j = 0; j < JN; j++) {
    float wj = ex2f(fmaxf(z[j], 0.2f * z[j]));
    if (CLAMP && (e + 2 * j + p >= end)) wj = 0.f;
    __half2 wh = __floats2half2_rn(wj, wj);
    const __half2* qh = reinterpret_cast<const __half2*>(&q[j]);
    hacc[0] = __hfma2(wh, qh[0], hacc[0]);
    hacc[1] = __hfma2(wh, qh[1], hacc[1]);
    hacc[2] = __hfma2(wh, qh[2], hacc[2]);
    hacc[3] = __hfma2(wh, qh[3], hacc[3]);
    S += wj;
  }
  // Fold half2 partials into packed fp32 accumulators
#pragma unroll
  for (int k = 0; k < 4; k++) {
    float2 t = __half22float2(hacc[k]);
    fadd2(acc2[k], pack2(t.x, t.y));
  }
}

__device__ __forceinline__ void agg_node(
    int node, int start, int end, float f1h, int p, int g, int hg,
    const int* __restrict__ dst, const uint4* __restrict__ fh4,
    float* __restrict__ out) {
  unsigned long long acc2[4] = {0ull, 0ull, 0ull, 0ull};
  float S = 0.f;

  if (end > start) {
    const int rem = (end - start) & 7;
    int e = start;
    const int efull = end - rem;
    for (; e < efull; e += 8)
      agg_batch<4, false>(e, end, f1h, p, g, hg, dst, fh4, acc2, S);
    if (rem) {
      if (rem <= 4)
        agg_batch<2, true>(e, end, f1h, p, g, hg, dst, fh4, acc2, S);
      else
        agg_batch<4, true>(e, end, f1h, p, g, hg, dst, fh4, acc2, S);
    }
  }

  float acc[8];
#pragma unroll
  for (int k = 0; k < 4; k++) unpack2(acc2[k], acc[2 * k], acc[2 * k + 1]);

  S += __shfl_xor_sync(0xffffffffu, S, 16);
#pragma unroll
  for (int k = 0; k < 8; k++) acc[k] += __shfl_xor_sync(0xffffffffu, acc[k], 16);

  float inv = (end > start) ? (1.f / S) : 0.f;
  const int base = p * 4;
  float4 o;
  o.x = acc[base + 0] * inv; o.y = acc[base + 1] * inv;
  o.z = acc[base + 2] * inv; o.w = acc[base + 3] * inv;
  o.x = o.x > 0.f ? o.x : (__expf(o.x) - 1.f);
  o.y = o.y > 0.f ? o.y : (__expf(o.y) - 1.f);
  o.z = o.z > 0.f ? o.z : (__expf(o.z) - 1.f);
  o.w = o.w > 0.f ? o.w : (__expf(o.w) - 1.f);
  reinterpret_cast<float4*>(out)[(size_t)node * 32 + g * 2 + p] = o;
}

__global__ __launch_bounds__(128) void agg_kernel(
    const int* __restrict__ dst, float* __restrict__ out, int n) {
  const int lane = threadIdx.x & 31;
  const int p  = lane >> 4;
  const int g  = lane & 15;
  const int hg = g >> 1;
  const uint4* fh4 = reinterpret_cast<const uint4*>(g_feats_h);

  for (;;) {
    int base = 0;
    if (lane == 0) base = atomicAdd(&g_ctr, 4);
    base = __shfl_sync(0xffffffffu, base, 0);
    if (base >= n) break;

    // Prefetch node descriptors: rowptr[base..base+4] + f1 for 4 nodes
    int rp = 0;
    if (lane < 5) {
      int idx = min(base + lane, n);
      rp = g_rowptr[idx];
    }
    const int r0 = __shfl_sync(0xffffffffu, rp, 0);
    const int r1 = __shfl_sync(0xffffffffu, rp, 1);
    const int r2 = __shfl_sync(0xffffffffu, rp, 2);
    const int r3 = __shfl_sync(0xffffffffu, rp, 3);
    const int r4 = __shfl_sync(0xffffffffu, rp, 4);
    float f1v[4];
#pragma unroll
    for (int i = 0; i < 4; i++)
      f1v[i] = (base + i < n) ? g_f1[(size_t)(base + i) * 8 + hg] : 0.f;

    const int lim = min(4, n - base);
    const int st[5] = {r0, r1, r2, r3, r4};
#pragma unroll
    for (int i = 0; i < 4; i++) {
      if (i < lim)
        agg_node(base + i, st[i], st[i + 1], f1v[i], p, g, hg, dst, fh4, out);
    }
  }
}

// ---------------------------------------------------------------------------
extern "C" void kernel_launch(void* const* d_in, const int* in_sizes, int n_in,
                              void* d_out, int out_size) {
  const float* x  = (const float*)d_in[0];
  const float* W  = (const float*)d_in[1];
  const float* a1 = (const float*)d_in[2];
  const float* b1 = (const float*)d_in[3];
  const float* a2 = (const float*)d_in[4];
  const float* b2 = (const float*)d_in[5];
  const int*  src = (const int*)d_in[6];
  const int*  dst = (const int*)d_in[7];
  float* out = (float*)d_out;

  const int n = in_sizes[0] / 128;   // N
  const int e = in_sizes[6];         // E

  const int rp_blocks = (e + 1023) / 1024;           // 4 edges/thread
  const int n_tiles   = (n + 63) / 64;
  const int feat_ctas = (n_tiles < FEAT_CTAS) ? n_tiles : FEAT_CTAS;

  cudaFuncSetAttribute(feat_rp_kernel, cudaFuncAttributeMaxDynamicSharedMemorySize,
                       SMEM_FEAT_TOTAL);

  feat_rp_kernel<<<feat_ctas + rp_blocks, 256, SMEM_FEAT_TOTAL>>>(
      x, W, a1, b1, a2, b2, src, n, e, rp_blocks, n_tiles, feat_ctas);
  agg_kernel<<<AGG_BLOCKS, 128>>>(dst, out, n);
}